// round 8
// baseline (speedup 1.0000x reference)
#include <cuda_runtime.h>
#include <cuda_bf16.h>

#define BB 1024
#define NN 8192
#define KK 4096
#define BN (BB * NN)

// Scratch: pos_map[n] = k if n == info_set[k] else -1
__device__ int g_posmap[NN];

__global__ void k_init_posmap() {
    int t = blockIdx.x * blockDim.x + threadIdx.x;
    if (t < NN) g_posmap[t] = -1;
}

__global__ void k_scatter_posmap(const int* __restrict__ info_set) {
    int t = blockIdx.x * blockDim.x + threadIdx.x;
    if (t < KK) g_posmap[info_set[t]] = t;
}

// One block per batch row. 256 threads.
// Phase 1: stream the row once: compute u/f, write f,u,p,r outputs, and
//          ballot-pack u bits into 256 uint32 words (1 KB smem).
// Phase 2: GF(2) superset-sum (zeta transform): 5 in-word stages + 8
//          word-stride stages in smem -> y[j] = XOR_{p superset of j} u[p].
// Phase 3: x[o] = y[rev13(o)]; with o = i*256 + t this is bit rev5(i) of
//          word rev8(t) -> one smem word per thread, 32 coalesced stores.
__global__ __launch_bounds__(256) void k_polar_main(
    const float* __restrict__ info_bits,
    const int*   __restrict__ u_random,
    float*       __restrict__ out)
{
    __shared__ unsigned sw[256];

    const int b    = blockIdx.x;
    const int t    = threadIdx.x;
    const int lane = t & 31;
    const int warp = t >> 5;

    const int*   ur_row = u_random  + (long long)b * NN;
    const float* ib_row = info_bits + (long long)b * KK;

    float*  out_x = out;
    float*  out_f = out + (long long)BN;
    float*  out_u = out + 2LL * BN;
    float2* out_p = (float2*)(out + 3LL * BN);
    float2* out_r = (float2*)(out + 5LL * BN);

    const long long rowbase = (long long)b * NN;

    // ---- Phase 1: easy outputs + bit packing ----
    #pragma unroll 4
    for (int i = 0; i < 32; i++) {
        int n  = i * 256 + t;            // warp covers 32 consecutive n
        int ur = ur_row[n];
        int k  = g_posmap[n];
        int uv = ur, fv = ur;
        if (k >= 0) {
            uv = (ib_row[k] > 0.5f) ? 1 : 0;
            fv = 2;
        }
        long long idx = rowbase + n;
        out_f[idx] = (float)fv;
        out_u[idx] = (float)uv;
        out_p[idx] = make_float2(0.5f, 0.5f);
        out_r[idx] = make_float2((float)(1 - ur), (float)ur);

        unsigned bal = __ballot_sync(0xFFFFFFFFu, uv);
        // in-word superset-sum stages (n-bits 0..4):
        // y[j] ^= y[j + 2^b] for positions with bit b clear
        bal ^= (bal >> 1)  & 0x55555555u;
        bal ^= (bal >> 2)  & 0x33333333u;
        bal ^= (bal >> 4)  & 0x0F0F0F0Fu;
        bal ^= (bal >> 8)  & 0x00FF00FFu;
        bal ^= (bal >> 16) & 0x0000FFFFu;
        if (lane == 0) sw[i * 8 + warp] = bal;   // word index = n>>5
    }
    __syncthreads();

    // ---- Phase 2: word-level stages (n-bits 5..12, word strides 1..128) ----
    // Within a stage: writers are bit-clear positions, readers read bit-set
    // positions (never written this stage) -> one sync per stage suffices.
    #pragma unroll
    for (int s = 1; s < 256; s <<= 1) {
        unsigned v = 0u;
        bool act = (t & s) == 0;
        if (act) v = sw[t + s];
        if (act) sw[t] ^= v;
        __syncthreads();
    }

    // ---- Phase 3: bit-reversed unpack, coalesced float stores ----
    unsigned W = sw[__brev((unsigned)t) >> 24];   // word rev8(t)
    #pragma unroll
    for (int i = 0; i < 32; i++) {
        int bit = (int)(__brev((unsigned)i) >> 27);   // rev5(i)
        out_x[rowbase + i * 256 + t] = (float)((W >> bit) & 1u);
    }
}

extern "C" void kernel_launch(void* const* d_in, const int* in_sizes, int n_in,
                              void* d_out, int out_size) {
    const float* info_bits = (const float*)d_in[0];  // (B, K) float32 0/1
    const int*   u_random  = (const int*)d_in[1];    // (B, N) int32 0/1
    const int*   info_set  = (const int*)d_in[2];    // (K,) sorted int32
    float* out = (float*)d_out;                      // 7*B*N float32

    k_init_posmap<<<NN / 256, 256>>>();
    k_scatter_posmap<<<KK / 256, 256>>>(info_set);
    k_polar_main<<<BB, 256>>>(info_bits, u_random, out);
}